// round 4
// baseline (speedup 1.0000x reference)
#include <cuda_runtime.h>
#include <cuda_bf16.h>
#include <cstdint>

#define BB  2
#define NN  16384
#define MM  4096
#define C1_ 128
#define C2_ 256
#define H1_ 256
#define H2_ 128

// ---------------------------------------------------------------------------
// Scratch
// ---------------------------------------------------------------------------
__device__ int3   g_idx[BB * NN];
__device__ float3 g_wts[BB * NN];
__device__ float  g_Gt[(size_t)BB * MM * H1_];   // (B, M, H1) point-major
__device__ float  g_Ut[(size_t)BB * NN * H1_];   // (B, N, H1) point-major
__device__ float  g_h [(size_t)BB * H1_ * NN];   // (B, H1, N) channel-major

// ---------------------------------------------------------------------------
// Small PTX helpers (all baseline sm_80-level: work on plain sm_103 target)
// ---------------------------------------------------------------------------
__device__ __forceinline__ uint32_t smem_u32(const void* p) {
    uint32_t a;
    asm("{ .reg .u64 t; cvta.to.shared.u64 t, %1; cvt.u32.u64 %0, t; }" : "=r"(a) : "l"(p));
    return a;
}
__device__ __forceinline__ void ldm_x4(uint32_t* r, uint32_t addr) {
    asm volatile("ldmatrix.sync.aligned.m8n8.x4.shared.b16 {%0,%1,%2,%3}, [%4];"
                 : "=r"(r[0]), "=r"(r[1]), "=r"(r[2]), "=r"(r[3]) : "r"(addr));
}
__device__ __forceinline__ void ldm_x2(uint32_t* r, uint32_t addr) {
    asm volatile("ldmatrix.sync.aligned.m8n8.x2.shared.b16 {%0,%1}, [%2];"
                 : "=r"(r[0]), "=r"(r[1]) : "r"(addr));
}
__device__ __forceinline__ void mma16816(float* d, const uint32_t* a, const uint32_t* b) {
    asm volatile("mma.sync.aligned.m16n8k16.row.col.f32.bf16.bf16.f32 "
                 "{%0,%1,%2,%3}, {%4,%5,%6,%7}, {%8,%9}, {%0,%1,%2,%3};"
                 : "+f"(d[0]), "+f"(d[1]), "+f"(d[2]), "+f"(d[3])
                 : "r"(a[0]), "r"(a[1]), "r"(a[2]), "r"(a[3]), "r"(b[0]), "r"(b[1]));
}

// ---------------------------------------------------------------------------
// kNN: 4 threads per query, FMA-only scoring (score = 0.5|b|^2 - a.b)
// ---------------------------------------------------------------------------
__device__ __forceinline__ void ins3(float d, int i,
                                     float& s0, float& s1, float& s2,
                                     int& i0, int& i1, int& i2) {
    if (d < s2) {
        if (d < s1) {
            s2 = s1; i2 = i1;
            if (d < s0) { s1 = s0; i1 = i0; s0 = d; i0 = i; }
            else        { s1 = d;  i1 = i; }
        } else { s2 = d; i2 = i; }
    }
}

__global__ void knn_kernel(const float* __restrict__ unknown,
                           const float* __restrict__ known,
                           int3* __restrict__ idx_out,
                           float3* __restrict__ wts_out)
{
    extern __shared__ float sm[];
    float* sx = sm;
    float* sy = sm + MM;
    float* sz = sm + 2 * MM;
    float* sh = sm + 3 * MM;

    const int b   = blockIdx.y;
    const int tid = threadIdx.x;

    const float* kb = known + (size_t)b * MM * 3;
    for (int i = tid; i < MM; i += blockDim.x) {
        float x = kb[i * 3 + 0], y = kb[i * 3 + 1], z = kb[i * 3 + 2];
        sx[i] = x; sy[i] = y; sz[i] = z;
        sh[i] = 0.5f * (x * x + y * y + z * z);
    }
    __syncthreads();

    const int q     = blockIdx.x * 64 + (tid >> 2);
    const int slice = tid & 3;

    const float3 a = ((const float3*)unknown)[(size_t)b * NN + q];
    const float nax = -a.x, nay = -a.y, naz = -a.z;

    float s0 = 1e30f, s1 = 1e30f, s2 = 1e30f;
    int i0 = 0, i1 = 0, i2 = 0;

    const float4* x4 = (const float4*)sx + slice * (MM / 16);
    const float4* y4 = (const float4*)sy + slice * (MM / 16);
    const float4* z4 = (const float4*)sz + slice * (MM / 16);
    const float4* h4 = (const float4*)sh + slice * (MM / 16);
    const int mbase = slice * (MM / 4);

    #pragma unroll 2
    for (int j = 0; j < MM / 16; j++) {
        float4 X = x4[j], Y = y4[j], Z = z4[j], H = h4[j];
        float t0 = fmaf(X.x, nax, fmaf(Y.x, nay, fmaf(Z.x, naz, H.x)));
        float t1 = fmaf(X.y, nax, fmaf(Y.y, nay, fmaf(Z.y, naz, H.y)));
        float t2 = fmaf(X.z, nax, fmaf(Y.z, nay, fmaf(Z.z, naz, H.z)));
        float t3 = fmaf(X.w, nax, fmaf(Y.w, nay, fmaf(Z.w, naz, H.w)));
        float m = fminf(fminf(t0, t1), fminf(t2, t3));
        if (m < s2) {
            int mb = mbase + j * 4;
            ins3(t0, mb + 0, s0, s1, s2, i0, i1, i2);
            ins3(t1, mb + 1, s0, s1, s2, i0, i1, i2);
            ins3(t2, mb + 2, s0, s1, s2, i0, i1, i2);
            ins3(t3, mb + 3, s0, s1, s2, i0, i1, i2);
        }
    }

    // merge across the 4 slices (adjacent lanes)
    #pragma unroll
    for (int delta = 1; delta <= 2; delta <<= 1) {
        float a0 = __shfl_xor_sync(0xFFFFFFFF, s0, delta);
        float a1 = __shfl_xor_sync(0xFFFFFFFF, s1, delta);
        float a2 = __shfl_xor_sync(0xFFFFFFFF, s2, delta);
        int b0 = __shfl_xor_sync(0xFFFFFFFF, i0, delta);
        int b1 = __shfl_xor_sync(0xFFFFFFFF, i1, delta);
        int b2 = __shfl_xor_sync(0xFFFFFFFF, i2, delta);
        ins3(a0, b0, s0, s1, s2, i0, i1, i2);
        ins3(a1, b1, s0, s1, s2, i0, i1, i2);
        ins3(a2, b2, s0, s1, s2, i0, i1, i2);
    }

    if (slice == 0) {
        // exact distances for the winners
        float dx, dy, dz;
        dx = sx[i0] - a.x; dy = sy[i0] - a.y; dz = sz[i0] - a.z;
        float d0 = dx * dx + dy * dy + dz * dz;
        dx = sx[i1] - a.x; dy = sy[i1] - a.y; dz = sz[i1] - a.z;
        float d1 = dx * dx + dy * dy + dz * dz;
        dx = sx[i2] - a.x; dy = sy[i2] - a.y; dz = sz[i2] - a.z;
        float d2 = dx * dx + dy * dy + dz * dz;

        float r0 = 1.0f / (sqrtf(d0) + 1e-8f);
        float r1 = 1.0f / (sqrtf(d1) + 1e-8f);
        float r2 = 1.0f / (sqrtf(d2) + 1e-8f);
        float rs = 1.0f / (r0 + r1 + r2);
        idx_out[(size_t)b * NN + q] = make_int3(i0, i1, i2);
        wts_out[(size_t)b * NN + q] = make_float3(r0 * rs, r1 * rs, r2 * rs);
    }
}

// ---------------------------------------------------------------------------
// mma.sync bf16-split GEMM.
//   D(P x O) = X^T (P,K) * W^T (K,O); fp32 accum; split fp32 = hi + lo bf16,
//   3 MMA passes per k-step: hh + hl + lh.
//   A operand rows = points (staged transpose from (K,P) input)
//   B operand rows = W rows (K contiguous = mma "col" layout, native)
//   Block tile 128x128, BK=64; 8 warps (2m x 4n), warp tile 64x32.
//   PTMAJOR=true : store D point-major (P, O) directly from fragments.
//   PTMAJOR=false: transpose through smem, store (O, P) with bias + ReLU.
// Smem: A hi/lo + B hi/lo, 144B row pitch (conflict-free ldmatrix).
// ---------------------------------------------------------------------------
constexpr int SA_HI = 0;
constexpr int SA_LO = 128 * 144;          // 18432
constexpr int SB_HI = 2 * 128 * 144;      // 36864
constexpr int SB_LO = 3 * 128 * 144;      // 55296
constexpr int GEMM_SMEM = 4 * 128 * 144;  // 73728

__device__ __forceinline__ void cvt_store(const float* v, char* shi, char* slo,
                                          int row, int khalf) {
    #pragma unroll
    for (int g = 0; g < 4; g++) {
        uint32_t hw[4], lw[4];
        #pragma unroll
        for (int qq = 0; qq < 4; qq++) {
            float x = v[g * 8 + qq * 2], y = v[g * 8 + qq * 2 + 1];
            __nv_bfloat16 xh = __float2bfloat16(x), yh = __float2bfloat16(y);
            float xr = x - __bfloat162float(xh), yr = y - __bfloat162float(yh);
            __nv_bfloat16 xl = __float2bfloat16(xr), yl = __float2bfloat16(yr);
            hw[qq] = (uint32_t)__bfloat16_as_ushort(xh) | ((uint32_t)__bfloat16_as_ushort(yh) << 16);
            lw[qq] = (uint32_t)__bfloat16_as_ushort(xl) | ((uint32_t)__bfloat16_as_ushort(yl) << 16);
        }
        int off = row * 144 + khalf * 64 + g * 16;
        *(uint4*)(shi + off) = make_uint4(hw[0], hw[1], hw[2], hw[3]);
        *(uint4*)(slo + off) = make_uint4(lw[0], lw[1], lw[2], lw[3]);
    }
}

template <bool PTMAJOR>
__global__ void __launch_bounds__(256, 1)
mma_gemm(const float* __restrict__ Xpts, long xStride, int P,
         const float* __restrict__ W, int ldW, int Ktot,
         float* __restrict__ C, long cStride, int ldC,
         const float* __restrict__ bias)
{
    extern __shared__ char smc[];
    char* sAhi = smc + SA_HI;
    char* sAlo = smc + SA_LO;
    char* sBhi = smc + SB_HI;
    char* sBlo = smc + SB_LO;

    const int tid = threadIdx.x, wid = tid >> 5, lane = tid & 31;
    const int wm = wid & 1, wn = wid >> 1;

    const float* Xb = Xpts + (long)blockIdx.z * xStride;
    float* Cb = C + (long)blockIdx.z * cStride;
    const int p0 = blockIdx.x * 128;
    const int o0 = blockIdx.y * 128;

    const int sp = tid & 127, khalf = tid >> 7;

    float acc[4][4][4] = {};

    const uint32_t aAhi = smem_u32(sAhi), aAlo = smem_u32(sAlo);
    const uint32_t aBhi = smem_u32(sBhi), aBlo = smem_u32(sBlo);

    for (int k0 = 0; k0 < Ktot; k0 += 64) {
        // ---- stage A: transpose-gather 128 points x 64 k ----
        {
            const float* src = Xb + (long)(k0 + khalf * 32) * P + p0 + sp;
            float v[32];
            #pragma unroll
            for (int kk = 0; kk < 32; kk++) v[kk] = src[(long)kk * P];
            cvt_store(v, sAhi, sAlo, sp, khalf);
        }
        // ---- stage B: 128 W rows x 64 k (k contiguous) ----
        {
            const float* src = W + (long)(o0 + sp) * ldW + k0 + khalf * 32;
            float v[32];
            #pragma unroll
            for (int kk = 0; kk < 8; kk++) {
                float4 f = *(const float4*)&src[kk * 4];
                v[kk * 4 + 0] = f.x; v[kk * 4 + 1] = f.y;
                v[kk * 4 + 2] = f.z; v[kk * 4 + 3] = f.w;
            }
            cvt_store(v, sBhi, sBlo, sp, khalf);
        }
        __syncthreads();

        // ---- compute: 4 k-steps of m16n8k16, 3 split passes ----
        const int amat = lane >> 3, ar8 = lane & 7;
        const int blm = (lane >> 3) & 1, bln = lane & 7;
        #pragma unroll
        for (int ks = 0; ks < 4; ks++) {
            uint32_t Ah[4][4], Al[4][4];
            #pragma unroll
            for (int mi = 0; mi < 4; mi++) {
                int row = wm * 64 + mi * 16 + (amat & 1) * 8 + ar8;
                uint32_t off = row * 144 + ks * 32 + (amat >> 1) * 16;
                ldm_x4(Ah[mi], aAhi + off);
                ldm_x4(Al[mi], aAlo + off);
            }
            uint32_t Bh[4][2], Bl[4][2];
            #pragma unroll
            for (int nj = 0; nj < 4; nj++) {
                int nrow = wn * 32 + nj * 8 + bln;
                uint32_t off = nrow * 144 + ks * 32 + blm * 16;
                ldm_x2(Bh[nj], aBhi + off);
                ldm_x2(Bl[nj], aBlo + off);
            }
            #pragma unroll
            for (int mi = 0; mi < 4; mi++)
                #pragma unroll
                for (int nj = 0; nj < 4; nj++) {
                    mma16816(acc[mi][nj], Ah[mi], Bh[nj]);
                    mma16816(acc[mi][nj], Ah[mi], Bl[nj]);
                    mma16816(acc[mi][nj], Al[mi], Bh[nj]);
                }
        }
        __syncthreads();
    }

    if (PTMAJOR) {
        // D fragment: row = point (groupID), cols = o pair -> (P, O) store
        #pragma unroll
        for (int mi = 0; mi < 4; mi++) {
            int prow = p0 + wm * 64 + mi * 16 + (lane >> 2);
            #pragma unroll
            for (int nj = 0; nj < 4; nj++) {
                int o = o0 + wn * 32 + nj * 8 + (lane & 3) * 2;
                float2 v0 = make_float2(acc[mi][nj][0], acc[mi][nj][1]);
                float2 v1 = make_float2(acc[mi][nj][2], acc[mi][nj][3]);
                *(float2*)&Cb[(long)prow * ldC + o] = v0;
                *(float2*)&Cb[(long)(prow + 8) * ldC + o] = v1;
            }
        }
    } else {
        // transpose through smem, write (O, P) with bias + relu
        float* tb = (float*)smc;   // 128 x 132 fp32
        #pragma unroll
        for (int mi = 0; mi < 4; mi++) {
            int pl = wm * 64 + mi * 16 + (lane >> 2);
            #pragma unroll
            for (int nj = 0; nj < 4; nj++) {
                int ol = wn * 32 + nj * 8 + (lane & 3) * 2;
                tb[ol * 132 + pl]           = acc[mi][nj][0];
                tb[(ol + 1) * 132 + pl]     = acc[mi][nj][1];
                tb[ol * 132 + pl + 8]       = acc[mi][nj][2];
                tb[(ol + 1) * 132 + pl + 8] = acc[mi][nj][3];
            }
        }
        __syncthreads();
        #pragma unroll 8
        for (int rep = 0; rep < 64; rep++) {
            int o = rep * 2 + khalf;
            float bi = bias[o0 + o];
            float v = fmaxf(tb[o * 132 + sp] + bi, 0.0f);
            Cb[(long)(o0 + o) * ldC + p0 + sp] = v;
        }
    }
}

// ---------------------------------------------------------------------------
// Combine: h[b,o,n] = relu( sum_j w_j * Gt[b,idx_j,o] + Ut[b,n,o] + b1[o] )
// ---------------------------------------------------------------------------
__global__ void combine_kernel(const float* __restrict__ Gt,
                               const float* __restrict__ Ut,
                               const int3* __restrict__ idx,
                               const float3* __restrict__ wts,
                               const float* __restrict__ b1,
                               float* __restrict__ h)
{
    __shared__ float smh[H1_][33];

    const int b    = blockIdx.y;
    const int n0   = blockIdx.x * 32;
    const int t    = threadIdx.x;
    const int warp = t >> 5;
    const int lane = t & 31;
    const int n    = n0 + warp;

    const int3   id = idx[(size_t)b * NN + n];
    const float3 ww = wts[(size_t)b * NN + n];

    const float* g0 = Gt + ((long)b * MM + id.x) * H1_;
    const float* g1 = Gt + ((long)b * MM + id.y) * H1_;
    const float* g2 = Gt + ((long)b * MM + id.z) * H1_;
    const float* ut = Ut + ((long)b * NN + n) * H1_;

    #pragma unroll
    for (int rep = 0; rep < 2; rep++) {
        int q = rep * 128 + lane * 4;
        float4 a  = *(const float4*)&g0[q];
        float4 bb = *(const float4*)&g1[q];
        float4 c  = *(const float4*)&g2[q];
        float4 u  = *(const float4*)&ut[q];
        float4 bv = *(const float4*)&b1[q];
        smh[q + 0][warp] = fmaxf(ww.x * a.x + ww.y * bb.x + ww.z * c.x + u.x + bv.x, 0.0f);
        smh[q + 1][warp] = fmaxf(ww.x * a.y + ww.y * bb.y + ww.z * c.y + u.y + bv.y, 0.0f);
        smh[q + 2][warp] = fmaxf(ww.x * a.z + ww.y * bb.z + ww.z * c.z + u.z + bv.z, 0.0f);
        smh[q + 3][warp] = fmaxf(ww.x * a.w + ww.y * bb.w + ww.z * c.w + u.w + bv.w, 0.0f);
    }
    __syncthreads();

    #pragma unroll
    for (int rep = 0; rep < 8; rep++) {
        int o = rep * 32 + warp;
        h[((long)b * H1_ + o) * NN + n0 + lane] = smh[o][lane];
    }
}

// ---------------------------------------------------------------------------
// Launch
// ---------------------------------------------------------------------------
extern "C" void kernel_launch(void* const* d_in, const int* in_sizes, int n_in,
                              void* d_out, int out_size)
{
    const float* unknown      = (const float*)d_in[0];
    const float* known        = (const float*)d_in[1];
    const float* unknow_feats = (const float*)d_in[2];
    const float* known_feats  = (const float*)d_in[3];
    const float* W1           = (const float*)d_in[4];
    const float* b1           = (const float*)d_in[5];
    const float* W2           = (const float*)d_in[6];
    const float* b2           = (const float*)d_in[7];
    float* out = (float*)d_out;

    void *pGt, *pUt, *pH, *pIdx, *pWts;
    cudaGetSymbolAddress(&pGt,  g_Gt);
    cudaGetSymbolAddress(&pUt,  g_Ut);
    cudaGetSymbolAddress(&pH,   g_h);
    cudaGetSymbolAddress(&pIdx, g_idx);
    cudaGetSymbolAddress(&pWts, g_wts);

    const int knn_smem = 4 * MM * 4;  // 64KB
    cudaFuncSetAttribute(knn_kernel, cudaFuncAttributeMaxDynamicSharedMemorySize, knn_smem);
    cudaFuncSetAttribute(mma_gemm<true>,  cudaFuncAttributeMaxDynamicSharedMemorySize, GEMM_SMEM);
    cudaFuncSetAttribute(mma_gemm<false>, cudaFuncAttributeMaxDynamicSharedMemorySize, GEMM_SMEM);

    // 1) 3-NN + weights (4 threads per query)
    knn_kernel<<<dim3(NN / 64, BB), 256, knn_smem>>>(unknown, known, (int3*)pIdx, (float3*)pWts);

    // 2) Gt[b,m,o] = sum_c W1[o,c] * known_feats[b,c,m]  (c in [0,256))
    mma_gemm<true><<<dim3(MM / 128, H1_ / 128, BB), 256, GEMM_SMEM>>>(
        known_feats, (long)C2_ * MM, MM, W1, C1_ + C2_, C2_,
        (float*)pGt, (long)MM * H1_, H1_, nullptr);

    // 3) Ut[b,n,o] = sum_c W1[o,256+c] * unknow_feats[b,c,n]
    mma_gemm<true><<<dim3(NN / 128, H1_ / 128, BB), 256, GEMM_SMEM>>>(
        unknow_feats, (long)C1_ * NN, NN, W1 + C2_, C1_ + C2_, C1_,
        (float*)pUt, (long)NN * H1_, H1_, nullptr);

    // 4) h = relu(gathered-weighted Gt + Ut + b1), stored (B, H1, N)
    combine_kernel<<<dim3(NN / 32, BB), 1024>>>(
        (const float*)pGt, (const float*)pUt, (const int3*)pIdx,
        (const float3*)pWts, b1, (float*)pH);

    // 5) out = relu(W2 @ h + b2), stored (B, H2, N)
    mma_gemm<false><<<dim3(NN / 128, H2_ / 128, BB), 256, GEMM_SMEM>>>(
        (const float*)pH, (long)H1_ * NN, NN, W2, H1_, H1_,
        out, (long)H2_ * NN, NN, b2);
}